// round 5
// baseline (speedup 1.0000x reference)
#include <cuda_runtime.h>
#include <cstdint>

// Problem constants
#define SD    16384          // S*D
#define NJ    22             // 14 alpha cols + 8 beta cols
#define NACC  23             // + sumsq
#define BN    2048           // B*N
#define NCHUNK 2             // k-split (8192 floats each)

typedef unsigned long long ull;

// Scratch (static __device__ arrays; no allocation)
__device__ __align__(16) float g_Wt[NJ * SD];        // Wt[j][k] = (gamma[k]+1)*W[k][j]
__device__ float g_part[NCHUNK][BN][NACC];           // per-chunk partial reductions
__device__ float g_M[BN * 64];                       // per-(b,n) 8x8 mixing matrix

__device__ __forceinline__ void fma2(ull &acc, ull a, ull b) {
    asm("fma.rn.f32x2 %0, %1, %2, %3;" : "=l"(acc) : "l"(a), "l"(b), "l"(acc));
}
__device__ __forceinline__ float f2sum(ull v) {
    float2 f = *reinterpret_cast<float2*>(&v);
    return f.x + f.y;
}
__device__ __forceinline__ float wsum(float v) {
    #pragma unroll
    for (int o = 16; o > 0; o >>= 1) v += __shfl_down_sync(0xffffffffu, v, o);
    return v;
}
__device__ __forceinline__ void cp_async16(uint32_t saddr, const void* gptr) {
    asm volatile("cp.async.cg.shared.global [%0], [%1], 16;\n" :: "r"(saddr), "l"(gptr));
}
__device__ __forceinline__ void cp_commit() {
    asm volatile("cp.async.commit_group;\n");
}

// ---------------------------------------------------------------------------
// Kernel P: build Wt[j][k] = (gamma[k]+1) * W[k][j]  (transposed, gamma-folded)
// ---------------------------------------------------------------------------
__global__ void k_prep(const float* __restrict__ gamma,
                       const float* __restrict__ Wa,
                       const float* __restrict__ Wb) {
    int i = blockIdx.x * blockDim.x + threadIdx.x;
    if (i >= NJ * SD) return;
    int j = i >> 14;          // / 16384
    int k = i & (SD - 1);
    float g = gamma[k] + 1.0f;
    float w = (j < 14) ? Wa[k * 14 + j] : Wb[k * 8 + (j - 14)];
    g_Wt[j * SD + k] = g * w;
}

// ---------------------------------------------------------------------------
// Kernel A: reductions. grid=(64, NCHUNK), 512 threads.
// Block = 32 bn x 8192-float k-chunk. Wt staged in smem (double-buffered
// cp.async tiles of 256 floats x 22 rows). j-dimension split across two
// warp-groups: warps 0-7 -> j[0,11)+sumsq, warps 8-15 -> j[11,22), both
// covering the same 32 bn (second group's residual LDGs are L1 hits).
// Accumulators <= 12 f32x2 per thread -> no spills, 4 warps/SMSP.
// ---------------------------------------------------------------------------
#define TKF   256                       // tile width in floats
#define TK16  64                        // tile width in 16B units
#define NTILE 32                        // 8192 / 256
#define TILE_U (NJ * TK16)              // 1408 16B units per tile

__global__ __launch_bounds__(512, 1) void k_reduce(const float* __restrict__ resid) {
    const int tid   = threadIdx.x;
    const int warp  = tid >> 5;
    const int lane  = tid & 31;
    const int chunk = blockIdx.y;
    const int grp   = warp >> 3;                  // 0 or 1 (j-group)
    const int wsub  = warp & 7;
    const int jb    = grp ? 11 : 0;               // j base for this group

    __shared__ __align__(16) float wts[2][NJ * TKF];   // 2 x 22528 B

    const int bn0 = blockIdx.x * 32 + wsub * 4;
    const ulonglong2* r16 = reinterpret_cast<const ulonglong2*>(resid);

    // per-bn base offsets in 16B units: b*4194304 + n*512
    uint32_t rb[4];
    #pragma unroll
    for (int c = 0; c < 4; c++) {
        int bn = bn0 + c;
        rb[c] = (uint32_t)(bn >> 10) * 4194304u + (uint32_t)(bn & 1023) * 512u;
    }

    // acc[c][0..10] = 11 w-dots; acc[c][11] = sumsq (group 0 only)
    ull acc[4][12];
    #pragma unroll
    for (int c = 0; c < 4; c++)
        #pragma unroll
        for (int j = 0; j < 12; j++) acc[c][j] = 0ull;

    const uint32_t sbase0 = (uint32_t)__cvta_generic_to_shared(&wts[0][0]);
    const uint32_t sbase1 = (uint32_t)__cvta_generic_to_shared(&wts[1][0]);
    const float* wsrc = g_Wt + chunk * 8192;

    // tile loader: 1408 16B units, 512 threads x up to 3
    auto load_tile = [&](int t, uint32_t sbase) {
        const float* src = wsrc + t * TKF;
        #pragma unroll
        for (int i = 0; i < 3; i++) {
            int u = tid + i * 512;
            if (u < TILE_U) {
                int j = u >> 6, pos = u & 63;
                cp_async16(sbase + u * 16, src + (size_t)j * SD + pos * 4);
            }
        }
        cp_commit();
    };

    load_tile(0, sbase0);

    #pragma unroll 1
    for (int t = 0; t < NTILE; t++) {
        if (t + 1 < NTILE) {
            load_tile(t + 1, ((t + 1) & 1) ? sbase1 : sbase0);
            asm volatile("cp.async.wait_group 1;\n");
        } else {
            asm volatile("cp.async.wait_group 0;\n");
        }
        __syncthreads();

        const ulonglong2* wt16 = reinterpret_cast<const ulonglong2*>(&wts[t & 1][0]);
        // global 16B index for this tile: k16 = chunk*2048 + t*64 + u
        const int k16b = chunk * 2048 + t * 64;
        const int s    = k16b >> 9;
        const uint32_t sadd = (uint32_t)s * 524288u + (uint32_t)(k16b & 511);

        #pragma unroll
        for (int m = 0; m < 2; m++) {
            const int u = m * 32 + lane;
            ulonglong2 rv[4];
            #pragma unroll
            for (int c = 0; c < 4; c++) rv[c] = r16[rb[c] + sadd + u];

            if (grp == 0) {
                #pragma unroll
                for (int c = 0; c < 4; c++) {
                    fma2(acc[c][11], rv[c].x, rv[c].x);
                    fma2(acc[c][11], rv[c].y, rv[c].y);
                }
            }
            #pragma unroll
            for (int j = 0; j < 11; j++) {
                ulonglong2 w = wt16[(jb + j) * TK16 + u];
                #pragma unroll
                for (int c = 0; c < 4; c++) {
                    fma2(acc[c][j], rv[c].x, w.x);
                    fma2(acc[c][j], rv[c].y, w.y);
                }
            }
        }
        __syncthreads();
    }

    // warp-reduce and store partials
    #pragma unroll
    for (int c = 0; c < 4; c++) {
        int bn = bn0 + c;
        #pragma unroll
        for (int j = 0; j < 11; j++) {
            float v = wsum(f2sum(acc[c][j]));
            if (lane == 0) g_part[chunk][bn][jb + j] = v;
        }
        if (grp == 0) {
            float v = wsum(f2sum(acc[c][11]));
            if (lane == 0) g_part[chunk][bn][22] = v;
        }
    }
}

// ---------------------------------------------------------------------------
// Kernel B: per-(b,n) scalar epilogue -> 8x8 mixing matrix M
// ---------------------------------------------------------------------------
__global__ void k_mix(const float* __restrict__ salpha,
                      const float* __restrict__ pbs,
                      const float* __restrict__ rscale,
                      const float* __restrict__ sbeta,
                      const float* __restrict__ hps) {
    int bn = blockIdx.x * blockDim.x + threadIdx.x;
    if (bn >= BN) return;

    float dot[NACC];
    #pragma unroll
    for (int j = 0; j < NACC; j++) {
        float v = 0.0f;
        #pragma unroll
        for (int sp = 0; sp < NCHUNK; sp++) v += g_part[sp][bn][j];
        dot[j] = v;
    }

    float scale = rsqrtf(fmaxf(dot[22], 1e-24f)) * 128.0f;  // sqrt(16384)=128
    float ps = pbs[0], rs = rscale[0], hp = hps[0];

    // w_pre = softmax(ps * dyn_pre + static_alpha[:8])
    float l[8], mx = -1e30f;
    #pragma unroll
    for (int i = 0; i < 8; i++) {
        l[i] = ps * (scale * dot[i]) + salpha[i];
        mx = fmaxf(mx, l[i]);
    }
    float e[8], sum = 0.0f;
    #pragma unroll
    for (int i = 0; i < 8; i++) { e[i] = expf(l[i] - mx); sum += e[i]; }
    float inv_sum = 1.0f / sum;
    float wpre[8];
    #pragma unroll
    for (int i = 0; i < 8; i++) wpre[i] = e[i] * inv_sum;

    // pairwise softmax first elements
    float p[3];
    #pragma unroll
    for (int k = 0; k < 3; k++) {
        float c0 = rs * (scale * dot[8 + 2 * k])     + salpha[8 + 2 * k];
        float c1 = rs * (scale * dot[8 + 2 * k + 1]) + salpha[8 + 2 * k + 1];
        p[k] = 1.0f / (1.0f + expf(c1 - c0));
    }
    // Kron: H[s][t] = h[s^t]
    float h[8];
    #pragma unroll
    for (int x = 0; x < 8; x++) {
        float f0 = (x & 4) ? (1.0f - p[0]) : p[0];
        float f1 = (x & 2) ? (1.0f - p[1]) : p[1];
        float f2 = (x & 1) ? (1.0f - p[2]) : p[2];
        h[x] = f0 * f1 * f2;
    }
    float beta[8];
    #pragma unroll
    for (int t = 0; t < 8; t++)
        beta[t] = 1.0f / (1.0f + expf(-(hp * (scale * dot[14 + t]) + sbeta[t])));

    float* Mo = &g_M[bn * 64];
    #pragma unroll
    for (int s = 0; s < 8; s++)
        #pragma unroll
        for (int t = 0; t < 8; t++)
            Mo[s * 8 + t] = h[s ^ t] + beta[t] * wpre[s];
}

// ---------------------------------------------------------------------------
// Kernel C: out[t,d] = sum_s M[s][t] * r[s,d].  grid=(BN, 2). Streaming
// cache hints: resid/out have zero reuse here.
// ---------------------------------------------------------------------------
__global__ __launch_bounds__(256) void k_apply(const float* __restrict__ resid,
                                               float* __restrict__ out) {
    const int bn = blockIdx.x;
    const int b = bn >> 10, n = bn & 1023;

    __shared__ float Ms[64];
    if (threadIdx.x < 64) Ms[threadIdx.x] = g_M[bn * 64 + threadIdx.x];
    __syncthreads();

    float M[64];
    #pragma unroll
    for (int i = 0; i < 64; i++) M[i] = Ms[i];

    const size_t base = (size_t)b * 16777216u + (size_t)n * 2048u;
    const int d = blockIdx.y * 1024 + threadIdx.x * 4;

    float4 acc[8];
    #pragma unroll
    for (int t = 0; t < 8; t++) acc[t] = make_float4(0.f, 0.f, 0.f, 0.f);

    #pragma unroll
    for (int s = 0; s < 8; s++) {
        float4 r4 = __ldcs(reinterpret_cast<const float4*>(resid + base + (size_t)s * 2097152u + d));
        #pragma unroll
        for (int t = 0; t < 8; t++) {
            float m = M[s * 8 + t];
            acc[t].x += m * r4.x;
            acc[t].y += m * r4.y;
            acc[t].z += m * r4.z;
            acc[t].w += m * r4.w;
        }
    }
    #pragma unroll
    for (int t = 0; t < 8; t++)
        __stcs(reinterpret_cast<float4*>(out + base + (size_t)t * 2097152u + d), acc[t]);
}

// ---------------------------------------------------------------------------
extern "C" void kernel_launch(void* const* d_in, const int* in_sizes, int n_in,
                              void* d_out, int out_size) {
    const float* resid  = (const float*)d_in[0];   // residuals (B*S, N, D)
    const float* gamma  = (const float*)d_in[1];   // (S*D,)
    const float* salpha = (const float*)d_in[2];   // (S+T,) = 14
    const float* Wa     = (const float*)d_in[3];   // (S*D, 14)
    const float* pbs    = (const float*)d_in[4];   // (1,)
    const float* rs     = (const float*)d_in[5];   // (1,)
    const float* sbeta  = (const float*)d_in[6];   // (S,) = 8
    const float* Wb     = (const float*)d_in[7];   // (S*D, 8)
    const float* hps    = (const float*)d_in[8];   // scalar
    float* out = (float*)d_out;

    k_prep<<<(NJ * SD + 255) / 256, 256>>>(gamma, Wa, Wb);
    k_reduce<<<dim3(BN / 32, NCHUNK), 512>>>(resid);
    k_mix<<<BN / 256, 256>>>(salpha, pbs, rs, sbeta, hps);
    k_apply<<<dim3(BN, 2), 256>>>(resid, out);
}

// round 6
// speedup vs baseline: 1.3215x; 1.3215x over previous
#include <cuda_runtime.h>
#include <cstdint>

// Problem constants
#define SD    16384          // S*D
#define NJ    22             // 14 alpha cols + 8 beta cols
#define NJP   11             // j-pairs
#define NACC  23             // + sumsq
#define BN    2048           // B*N
#define NCHUNK 2             // k-split (8192 floats each)

typedef unsigned long long ull;

// g_Wp layout: [plane 0/1][jp 0..10][u16 0..4095] of 16B units.
// plane p, unit u holds floats { w_{2jp}[4u+2p], w_{2jp+1}[4u+2p],
//                                w_{2jp}[4u+2p+1], w_{2jp+1}[4u+2p+1] }
// (gamma folded in). 2*11*4096 units = 360448 floats.
__device__ __align__(16) float g_Wp[2 * NJP * 4096 * 4];
__device__ float g_part[NCHUNK][BN][NACC];
__device__ float g_M[BN * 64];

__device__ __forceinline__ void fma2(ull &acc, ull a, ull b) {
    asm("fma.rn.f32x2 %0, %1, %2, %3;" : "=l"(acc) : "l"(a), "l"(b), "l"(acc));
}
__device__ __forceinline__ ull bcast(float r) {
    ull d; asm("mov.b64 %0, {%1, %1};" : "=l"(d) : "f"(r)); return d;
}
__device__ __forceinline__ float f2sum(ull v) {
    float2 f = *reinterpret_cast<float2*>(&v);
    return f.x + f.y;
}
__device__ __forceinline__ float wsum(float v) {
    #pragma unroll
    for (int o = 16; o > 0; o >>= 1) v += __shfl_down_sync(0xffffffffu, v, o);
    return v;
}
__device__ __forceinline__ float2 wsum2(ull v) {
    float2 f = *reinterpret_cast<float2*>(&v);
    #pragma unroll
    for (int o = 16; o > 0; o >>= 1) {
        f.x += __shfl_down_sync(0xffffffffu, f.x, o);
        f.y += __shfl_down_sync(0xffffffffu, f.y, o);
    }
    return f;
}
__device__ __forceinline__ void cp_async16(uint32_t saddr, const void* gptr) {
    asm volatile("cp.async.cg.shared.global [%0], [%1], 16;\n" :: "r"(saddr), "l"(gptr));
}
__device__ __forceinline__ void cp_commit() {
    asm volatile("cp.async.commit_group;\n");
}

// ---------------------------------------------------------------------------
// Kernel P: build paired/planar Wt. One thread per 16B output unit (90112).
// ---------------------------------------------------------------------------
__global__ void k_prep(const float* __restrict__ gamma,
                       const float* __restrict__ Wa,
                       const float* __restrict__ Wb) {
    int i = blockIdx.x * blockDim.x + threadIdx.x;
    if (i >= 2 * NJP * 4096) return;
    int plane = i / (NJP * 4096);
    int rem   = i - plane * (NJP * 4096);
    int jp    = rem >> 12;
    int u     = rem & 4095;
    int k0 = 4 * u + 2 * plane;
    int k1 = k0 + 1;
    float g0 = gamma[k0] + 1.0f;
    float g1 = gamma[k1] + 1.0f;
    float w00, w01, w10, w11;
    if (jp < 7) {
        w00 = Wa[(size_t)k0 * 14 + 2 * jp];
        w01 = Wa[(size_t)k0 * 14 + 2 * jp + 1];
        w10 = Wa[(size_t)k1 * 14 + 2 * jp];
        w11 = Wa[(size_t)k1 * 14 + 2 * jp + 1];
    } else {
        int c = 2 * (jp - 7);
        w00 = Wb[(size_t)k0 * 8 + c];
        w01 = Wb[(size_t)k0 * 8 + c + 1];
        w10 = Wb[(size_t)k1 * 8 + c];
        w11 = Wb[(size_t)k1 * 8 + c + 1];
    }
    float4 o = make_float4(g0 * w00, g0 * w01, g1 * w10, g1 * w11);
    *reinterpret_cast<float4*>(g_Wp + (size_t)i * 4) = o;
}

// ---------------------------------------------------------------------------
// Kernel A: reductions. grid=(64, NCHUNK), 256 threads, 32 bn/block,
// 4 bn/warp. Wt staged in smem (double-buffered cp.async, 22.5 KB tiles,
// paired/planar layout -> conflict-free LDS.128, f32x2 operands ready).
// Accumulators: 4bn x 11jp f32x2 + 4 sumsq f32x2 = 104 regs, no spills.
// ---------------------------------------------------------------------------
#define TKU    64                        // tile width in 16B k-units (256 floats)
#define NTILE  32                        // 2048 / 64
#define TILE_U (2 * NJP * TKU)           // 1408 16B units per tile

__global__ __launch_bounds__(256, 1) void k_reduce(const float* __restrict__ resid) {
    const int tid   = threadIdx.x;
    const int warp  = tid >> 5;
    const int lane  = tid & 31;
    const int chunk = blockIdx.y;

    __shared__ __align__(16) float wts[2][TILE_U * 4];   // 2 x 22528 B

    const int bn0 = blockIdx.x * 32 + warp * 4;
    const ulonglong2* r16 = reinterpret_cast<const ulonglong2*>(resid);

    uint32_t rb[4];
    #pragma unroll
    for (int c = 0; c < 4; c++) {
        int bn = bn0 + c;
        rb[c] = (uint32_t)(bn >> 10) * 4194304u + (uint32_t)(bn & 1023) * 512u;
    }

    ull acc[4][NJP];
    ull ss[4];
    #pragma unroll
    for (int c = 0; c < 4; c++) {
        ss[c] = 0ull;
        #pragma unroll
        for (int jp = 0; jp < NJP; jp++) acc[c][jp] = 0ull;
    }

    const uint32_t sbase0 = (uint32_t)__cvta_generic_to_shared(&wts[0][0]);
    const uint32_t sbase1 = (uint32_t)__cvta_generic_to_shared(&wts[1][0]);

    // tile loader: 1408 16B units, 256 threads x up to 6
    auto load_tile = [&](int t, uint32_t sbase) {
        const int g0 = chunk * 2048 + t * TKU;
        #pragma unroll
        for (int i = 0; i < 6; i++) {
            int v = tid + i * 256;
            if (v < TILE_U) {
                int plane = v / (NJP * TKU);
                int rem   = v - plane * (NJP * TKU);
                int jp    = rem >> 6;
                int pos   = rem & 63;
                size_t srcu = (size_t)plane * (NJP * 4096) + (size_t)jp * 4096 + g0 + pos;
                cp_async16(sbase + v * 16, g_Wp + srcu * 4);
            }
        }
        cp_commit();
    };

    load_tile(0, sbase0);

    #pragma unroll 1
    for (int t = 0; t < NTILE; t++) {
        // residual 16B index for this tile
        const int k16b = chunk * 2048 + t * TKU;
        const int s    = k16b >> 9;
        const uint32_t sadd = (uint32_t)s * 524288u + (uint32_t)(k16b & 511);

        // issue residual LDGs for both m-halves BEFORE waiting on cp.async
        ulonglong2 rvA[4], rvB[4];
        #pragma unroll
        for (int c = 0; c < 4; c++) rvA[c] = r16[rb[c] + sadd + lane];
        #pragma unroll
        for (int c = 0; c < 4; c++) rvB[c] = r16[rb[c] + sadd + 32 + lane];

        if (t + 1 < NTILE) {
            load_tile(t + 1, ((t + 1) & 1) ? sbase1 : sbase0);
            asm volatile("cp.async.wait_group 1;\n");
        } else {
            asm volatile("cp.async.wait_group 0;\n");
        }
        __syncthreads();

        const ulonglong2* wb = reinterpret_cast<const ulonglong2*>(&wts[t & 1][0]);

        #pragma unroll
        for (int m = 0; m < 2; m++) {
            const int u = m * 32 + lane;
            ulonglong2 rv[4];
            #pragma unroll
            for (int c = 0; c < 4; c++) rv[c] = m ? rvB[c] : rvA[c];

            // sumsq (f32x2)
            #pragma unroll
            for (int c = 0; c < 4; c++) {
                fma2(ss[c], rv[c].x, rv[c].x);
                fma2(ss[c], rv[c].y, rv[c].y);
            }
            // broadcasts: bc[c][kk] = (r,r) for the 4 k values of this unit
            ull bc[4][4];
            #pragma unroll
            for (int c = 0; c < 4; c++) {
                float2 lo = *reinterpret_cast<float2*>(&rv[c].x);
                float2 hi = *reinterpret_cast<float2*>(&rv[c].y);
                bc[c][0] = bcast(lo.x); bc[c][1] = bcast(lo.y);
                bc[c][2] = bcast(hi.x); bc[c][3] = bcast(hi.y);
            }
            #pragma unroll
            for (int jp = 0; jp < NJP; jp++) {
                ulonglong2 q0 = wb[jp * TKU + u];              // pairs for k0,k1
                ulonglong2 q1 = wb[NJP * TKU + jp * TKU + u];  // pairs for k2,k3
                #pragma unroll
                for (int c = 0; c < 4; c++) {
                    fma2(acc[c][jp], bc[c][0], q0.x);
                    fma2(acc[c][jp], bc[c][1], q0.y);
                    fma2(acc[c][jp], bc[c][2], q1.x);
                    fma2(acc[c][jp], bc[c][3], q1.y);
                }
            }
        }
        __syncthreads();
    }

    // warp-reduce and store partials (acc halves are DIFFERENT j: no cross-sum)
    #pragma unroll
    for (int c = 0; c < 4; c++) {
        int bn = bn0 + c;
        #pragma unroll
        for (int jp = 0; jp < NJP; jp++) {
            float2 v = wsum2(acc[c][jp]);
            if (lane == 0) {
                g_part[chunk][bn][2 * jp]     = v.x;
                g_part[chunk][bn][2 * jp + 1] = v.y;
            }
        }
        float sv = wsum(f2sum(ss[c]));
        if (lane == 0) g_part[chunk][bn][22] = sv;
    }
}

// ---------------------------------------------------------------------------
// Kernel B: per-(b,n) scalar epilogue -> 8x8 mixing matrix M
// ---------------------------------------------------------------------------
__global__ void k_mix(const float* __restrict__ salpha,
                      const float* __restrict__ pbs,
                      const float* __restrict__ rscale,
                      const float* __restrict__ sbeta,
                      const float* __restrict__ hps) {
    int bn = blockIdx.x * blockDim.x + threadIdx.x;
    if (bn >= BN) return;

    float dot[NACC];
    #pragma unroll
    for (int j = 0; j < NACC; j++) {
        float v = 0.0f;
        #pragma unroll
        for (int sp = 0; sp < NCHUNK; sp++) v += g_part[sp][bn][j];
        dot[j] = v;
    }

    float scale = rsqrtf(fmaxf(dot[22], 1e-24f)) * 128.0f;  // sqrt(16384)=128
    float ps = pbs[0], rs = rscale[0], hp = hps[0];

    // w_pre = softmax(ps * dyn_pre + static_alpha[:8])
    float l[8], mx = -1e30f;
    #pragma unroll
    for (int i = 0; i < 8; i++) {
        l[i] = ps * (scale * dot[i]) + salpha[i];
        mx = fmaxf(mx, l[i]);
    }
    float e[8], sum = 0.0f;
    #pragma unroll
    for (int i = 0; i < 8; i++) { e[i] = expf(l[i] - mx); sum += e[i]; }
    float inv_sum = 1.0f / sum;
    float wpre[8];
    #pragma unroll
    for (int i = 0; i < 8; i++) wpre[i] = e[i] * inv_sum;

    // pairwise softmax first elements
    float p[3];
    #pragma unroll
    for (int k = 0; k < 3; k++) {
        float c0 = rs * (scale * dot[8 + 2 * k])     + salpha[8 + 2 * k];
        float c1 = rs * (scale * dot[8 + 2 * k + 1]) + salpha[8 + 2 * k + 1];
        p[k] = 1.0f / (1.0f + expf(c1 - c0));
    }
    // Kron: H[s][t] = h[s^t]
    float h[8];
    #pragma unroll
    for (int x = 0; x < 8; x++) {
        float f0 = (x & 4) ? (1.0f - p[0]) : p[0];
        float f1 = (x & 2) ? (1.0f - p[1]) : p[1];
        float f2 = (x & 1) ? (1.0f - p[2]) : p[2];
        h[x] = f0 * f1 * f2;
    }
    float beta[8];
    #pragma unroll
    for (int t = 0; t < 8; t++)
        beta[t] = 1.0f / (1.0f + expf(-(hp * (scale * dot[14 + t]) + sbeta[t])));

    float* Mo = &g_M[bn * 64];
    #pragma unroll
    for (int s = 0; s < 8; s++)
        #pragma unroll
        for (int t = 0; t < 8; t++)
            Mo[s * 8 + t] = h[s ^ t] + beta[t] * wpre[s];
}

// ---------------------------------------------------------------------------
// Kernel C: out[t,d] = sum_s M[s][t] * r[s,d].  grid=(BN, 2).
// ---------------------------------------------------------------------------
__global__ __launch_bounds__(256) void k_apply(const float* __restrict__ resid,
                                               float* __restrict__ out) {
    const int bn = blockIdx.x;
    const int b = bn >> 10, n = bn & 1023;

    __shared__ float Ms[64];
    if (threadIdx.x < 64) Ms[threadIdx.x] = g_M[bn * 64 + threadIdx.x];
    __syncthreads();

    float M[64];
    #pragma unroll
    for (int i = 0; i < 64; i++) M[i] = Ms[i];

    const size_t base = (size_t)b * 16777216u + (size_t)n * 2048u;
    const int d = blockIdx.y * 1024 + threadIdx.x * 4;

    float4 acc[8];
    #pragma unroll
    for (int t = 0; t < 8; t++) acc[t] = make_float4(0.f, 0.f, 0.f, 0.f);

    #pragma unroll
    for (int s = 0; s < 8; s++) {
        float4 r4 = *reinterpret_cast<const float4*>(resid + base + (size_t)s * 2097152u + d);
        #pragma unroll
        for (int t = 0; t < 8; t++) {
            float m = M[s * 8 + t];
            acc[t].x += m * r4.x;
            acc[t].y += m * r4.y;
            acc[t].z += m * r4.z;
            acc[t].w += m * r4.w;
        }
    }
    #pragma unroll
    for (int t = 0; t < 8; t++)
        *reinterpret_cast<float4*>(out + base + (size_t)t * 2097152u + d) = acc[t];
}

// ---------------------------------------------------------------------------
extern "C" void kernel_launch(void* const* d_in, const int* in_sizes, int n_in,
                              void* d_out, int out_size) {
    const float* resid  = (const float*)d_in[0];   // residuals (B*S, N, D)
    const float* gamma  = (const float*)d_in[1];   // (S*D,)
    const float* salpha = (const float*)d_in[2];   // (S+T,) = 14
    const float* Wa     = (const float*)d_in[3];   // (S*D, 14)
    const float* pbs    = (const float*)d_in[4];   // (1,)
    const float* rs     = (const float*)d_in[5];   // (1,)
    const float* sbeta  = (const float*)d_in[6];   // (S,) = 8
    const float* Wb     = (const float*)d_in[7];   // (S*D, 8)
    const float* hps    = (const float*)d_in[8];   // scalar
    float* out = (float*)d_out;

    k_prep<<<(2 * NJP * 4096 + 255) / 256, 256>>>(gamma, Wa, Wb);
    k_reduce<<<dim3(BN / 32, NCHUNK), 256>>>(resid);
    k_mix<<<BN / 256, 256>>>(salpha, pbs, rs, sbeta, hps);
    k_apply<<<dim3(BN, 2), 256>>>(resid, out);
}

// round 8
// speedup vs baseline: 1.5749x; 1.1917x over previous
#include <cuda_runtime.h>
#include <cuda_bf16.h>
#include <cstdint>

// Problem constants
#define SD      16384        // S*D
#define NJ      22           // 14 alpha cols + 8 beta cols
#define NJP     24           // padded (2 zero cols)
#define BN      2048         // B*N
#define KC      8            // k-chunks (2048 floats each, == s index)
#define MT      16           // m-tiles of 128 bn
#define NTILE   32           // 64-k tiles per chunk
#define KT_TOT  256          // total 64-k tiles (SD/64)

typedef unsigned long long ull;

// g_Wf: B operand pre-baked in mma.m16n8k16 B-fragment layout.
// [kt][ks 0..3][ng 0..2][lane 0..31] -> uint2 {b0, b1}:
//   j = ng*8 + lane/4,  k0 = kt*64 + ks*16 + (lane%4)*2
//   b0 = bf16x2( w[j][k0],   w[j][k0+1] )   (low half = even k)
//   b1 = bf16x2( w[j][k0+8], w[j][k0+9] )
// with w[j][k] = (gamma[k]+1) * W[k][j], j>=22 -> 0.
__device__ __align__(16) uint2 g_Wf[KT_TOT * 12 * 32];
__device__ float g_part[KC][BN][NJP];
__device__ float g_ss[KC][BN];
__device__ float g_M[BN * 64];

__device__ __forceinline__ uint32_t pack_bf16x2(float lo, float hi) {
    __nv_bfloat162 h = __float22bfloat162_rn(make_float2(lo, hi));
    return *reinterpret_cast<uint32_t*>(&h);
}

__device__ __forceinline__ void mma_bf16(float* d, const uint32_t* a, uint2 b) {
    asm volatile(
        "mma.sync.aligned.m16n8k16.row.col.f32.bf16.bf16.f32 "
        "{%0,%1,%2,%3}, {%4,%5,%6,%7}, {%8,%9}, {%0,%1,%2,%3};"
        : "+f"(d[0]), "+f"(d[1]), "+f"(d[2]), "+f"(d[3])
        : "r"(a[0]), "r"(a[1]), "r"(a[2]), "r"(a[3]), "r"(b.x), "r"(b.y));
}

// ---------------------------------------------------------------------------
// Kernel P: bake B fragments (gamma folded, bf16). One thread per uint2.
// ---------------------------------------------------------------------------
__global__ void k_prepW(const float* __restrict__ gamma,
                        const float* __restrict__ Wa,
                        const float* __restrict__ Wb) {
    int i = blockIdx.x * blockDim.x + threadIdx.x;
    if (i >= KT_TOT * 12 * 32) return;
    int kt   = i / 384;
    int rem  = i - kt * 384;
    int ks   = rem >> 5 >> 2;        // rem/128? no: rem in [0,384): ks = rem/96
    ks       = rem / 96;
    int ng   = (rem / 32) % 3;
    int lane = rem & 31;
    int quad = lane >> 2, pos = lane & 3;
    int j  = ng * 8 + quad;
    int k0 = kt * 64 + ks * 16 + pos * 2;

    float w[4] = {0.f, 0.f, 0.f, 0.f};
    if (j < 22) {
        #pragma unroll
        for (int e = 0; e < 4; e++) {
            int k = k0 + (e >> 1) * 8 + (e & 1);
            float ww = (j < 14) ? Wa[(size_t)k * 14 + j] : Wb[(size_t)k * 8 + (j - 14)];
            w[e] = (gamma[k] + 1.0f) * ww;
        }
    }
    g_Wf[i] = make_uint2(pack_bf16x2(w[0], w[1]), pack_bf16x2(w[2], w[3]));
}

// ---------------------------------------------------------------------------
// Kernel A: tensor-core reductions via warp-level bf16 mma.sync.
// grid=(MT, KC), 256 threads. Warp w owns rows [w*16, w*16+16) of the
// 128-bn m-tile, scanning 2048 k (chunk). No smem, no syncs.
// ---------------------------------------------------------------------------
__global__ __launch_bounds__(256, 1) void k_reduce(const float* __restrict__ resid) {
    const int warp = threadIdx.x >> 5;
    const int lane = threadIdx.x & 31;
    const int quad = lane >> 2, pos = lane & 3;
    const int mt = blockIdx.x, chunk = blockIdx.y;
    const int b = mt >> 3, nbase = (mt & 7) * 128;

    const int row_lo = warp * 16 + quad;       // fragment rows quad / quad+8
    const float2* r2 = reinterpret_cast<const float2*>(resid);
    const size_t off_lo = (size_t)b * 8388608u + (size_t)chunk * 1048576u
                        + (size_t)(nbase + row_lo) * 1024u;
    const size_t off_hi = off_lo + 8u * 1024u;

    float acc[3][4];
    #pragma unroll
    for (int ng = 0; ng < 3; ng++)
        #pragma unroll
        for (int e = 0; e < 4; e++) acc[ng][e] = 0.0f;
    float ss_lo = 0.0f, ss_hi = 0.0f;

    #pragma unroll 1
    for (int t = 0; t < NTILE; t++) {
        // A loads: 16 float2, all independent (MLP=16)
        float2 av[4][4];
        const int kb2 = t * 32 + pos;          // float2 index of k = t*64+pos*2
        #pragma unroll
        for (int ks = 0; ks < 4; ks++) {
            const int c0 = kb2 + ks * 8;
            av[ks][0] = r2[off_lo + c0];
            av[ks][1] = r2[off_hi + c0];
            av[ks][2] = r2[off_lo + c0 + 4];   // k+8
            av[ks][3] = r2[off_hi + c0 + 4];
        }
        // B fragments: 12 coalesced uint2 (L1/L2-resident, shared by all warps)
        uint2 bv[12];
        const uint2* wt = g_Wf + (size_t)(chunk * NTILE + t) * 384 + lane;
        #pragma unroll
        for (int i = 0; i < 12; i++) bv[i] = wt[i * 32];

        #pragma unroll
        for (int ks = 0; ks < 4; ks++) {
            // fp32 sumsq from the same registers
            ss_lo = fmaf(av[ks][0].x, av[ks][0].x, ss_lo);
            ss_lo = fmaf(av[ks][0].y, av[ks][0].y, ss_lo);
            ss_lo = fmaf(av[ks][2].x, av[ks][2].x, ss_lo);
            ss_lo = fmaf(av[ks][2].y, av[ks][2].y, ss_lo);
            ss_hi = fmaf(av[ks][1].x, av[ks][1].x, ss_hi);
            ss_hi = fmaf(av[ks][1].y, av[ks][1].y, ss_hi);
            ss_hi = fmaf(av[ks][3].x, av[ks][3].x, ss_hi);
            ss_hi = fmaf(av[ks][3].y, av[ks][3].y, ss_hi);
            // cvt -> bf16 A fragment
            uint32_t a[4];
            a[0] = pack_bf16x2(av[ks][0].x, av[ks][0].y);
            a[1] = pack_bf16x2(av[ks][1].x, av[ks][1].y);
            a[2] = pack_bf16x2(av[ks][2].x, av[ks][2].y);
            a[3] = pack_bf16x2(av[ks][3].x, av[ks][3].y);
            #pragma unroll
            for (int ng = 0; ng < 3; ng++)
                mma_bf16(acc[ng], a, bv[ks * 3 + ng]);
        }
    }

    // store dot partials: D frag (m16n8): c0,c1 -> row quad, cols pos*2,+1
    const int bn_lo = mt * 128 + row_lo;
    #pragma unroll
    for (int ng = 0; ng < 3; ng++) {
        const int j0 = ng * 8 + pos * 2;
        *reinterpret_cast<float2*>(&g_part[chunk][bn_lo][j0]) =
            make_float2(acc[ng][0], acc[ng][1]);
        *reinterpret_cast<float2*>(&g_part[chunk][bn_lo + 8][j0]) =
            make_float2(acc[ng][2], acc[ng][3]);
    }
    // sumsq: reduce across the 4 lanes sharing this quad
    #pragma unroll
    for (int o = 1; o < 4; o <<= 1) {
        ss_lo += __shfl_xor_sync(0xffffffffu, ss_lo, o, 4);
        ss_hi += __shfl_xor_sync(0xffffffffu, ss_hi, o, 4);
    }
    if (pos == 0) {
        g_ss[chunk][bn_lo]     = ss_lo;
        g_ss[chunk][bn_lo + 8] = ss_hi;
    }
}

// ---------------------------------------------------------------------------
// Kernel B: per-(b,n) scalar epilogue -> 8x8 mixing matrix M
// ---------------------------------------------------------------------------
__global__ void k_mix(const float* __restrict__ salpha,
                      const float* __restrict__ pbs,
                      const float* __restrict__ rscale,
                      const float* __restrict__ sbeta,
                      const float* __restrict__ hps) {
    int bn = blockIdx.x * blockDim.x + threadIdx.x;
    if (bn >= BN) return;

    float dot[NJ];
    #pragma unroll
    for (int j = 0; j < NJ; j++) {
        float v = 0.0f;
        #pragma unroll
        for (int c = 0; c < KC; c++) v += g_part[c][bn][j];
        dot[j] = v;
    }
    float sumsq = 0.0f;
    #pragma unroll
    for (int c = 0; c < KC; c++) sumsq += g_ss[c][bn];

    float scale = rsqrtf(fmaxf(sumsq, 1e-24f)) * 128.0f;  // sqrt(16384)=128
    float ps = pbs[0], rs = rscale[0], hp = hps[0];

    // w_pre = softmax(ps * dyn_pre + static_alpha[:8])
    float l[8], mx = -1e30f;
    #pragma unroll
    for (int i = 0; i < 8; i++) {
        l[i] = ps * (scale * dot[i]) + salpha[i];
        mx = fmaxf(mx, l[i]);
    }
    float e[8], sum = 0.0f;
    #pragma unroll
    for (int i = 0; i < 8; i++) { e[i] = expf(l[i] - mx); sum += e[i]; }
    float inv_sum = 1.0f / sum;
    float wpre[8];
    #pragma unroll
    for (int i = 0; i < 8; i++) wpre[i] = e[i] * inv_sum;

    // pairwise softmax first elements
    float p[3];
    #pragma unroll
    for (int k = 0; k < 3; k++) {
        float c0 = rs * (scale * dot[8 + 2 * k])     + salpha[8 + 2 * k];
        float c1 = rs * (scale * dot[8 + 2 * k + 1]) + salpha[8 + 2 * k + 1];
        p[k] = 1.0f / (1.0f + expf(c1 - c0));
    }
    // Kron: H[s][t] = h[s^t]
    float h[8];
    #pragma unroll
    for (int x = 0; x < 8; x++) {
        float f0 = (x & 4) ? (1.0f - p[0]) : p[0];
        float f1 = (x & 2) ? (1.0f - p[1]) : p[1];
        float f2 = (x & 1) ? (1.0f - p[2]) : p[2];
        h[x] = f0 * f1 * f2;
    }
    float beta[8];
    #pragma unroll
    for (int t = 0; t < 8; t++)
        beta[t] = 1.0f / (1.0f + expf(-(hp * (scale * dot[14 + t]) + sbeta[t])));

    float* Mo = &g_M[bn * 64];
    #pragma unroll
    for (int s = 0; s < 8; s++)
        #pragma unroll
        for (int t = 0; t < 8; t++)
            Mo[s * 8 + t] = h[s ^ t] + beta[t] * wpre[s];
}

// ---------------------------------------------------------------------------
// Kernel C: out[t,d] = sum_s M[s][t] * r[s,d].  grid=(BN, 2). fp32 residuals.
// ---------------------------------------------------------------------------
__global__ __launch_bounds__(256) void k_apply(const float* __restrict__ resid,
                                               float* __restrict__ out) {
    const int bn = blockIdx.x;
    const int b = bn >> 10, n = bn & 1023;

    __shared__ float Ms[64];
    if (threadIdx.x < 64) Ms[threadIdx.x] = g_M[bn * 64 + threadIdx.x];
    __syncthreads();

    float M[64];
    #pragma unroll
    for (int i = 0; i < 64; i++) M[i] = Ms[i];

    const size_t base = (size_t)b * 16777216u + (size_t)n * 2048u;
    const int d = blockIdx.y * 1024 + threadIdx.x * 4;

    float4 acc[8];
    #pragma unroll
    for (int t = 0; t < 8; t++) acc[t] = make_float4(0.f, 0.f, 0.f, 0.f);

    #pragma unroll
    for (int s = 0; s < 8; s++) {
        float4 r4 = *reinterpret_cast<const float4*>(resid + base + (size_t)s * 2097152u + d);
        #pragma unroll
        for (int t = 0; t < 8; t++) {
            float m = M[s * 8 + t];
            acc[t].x += m * r4.x;
            acc[t].y += m * r4.y;
            acc[t].z += m * r4.z;
            acc[t].w += m * r4.w;
        }
    }
    #pragma unroll
    for (int t = 0; t < 8; t++)
        *reinterpret_cast<float4*>(out + base + (size_t)t * 2097152u + d) = acc[t];
}

// ---------------------------------------------------------------------------
extern "C" void kernel_launch(void* const* d_in, const int* in_sizes, int n_in,
                              void* d_out, int out_size) {
    const float* resid  = (const float*)d_in[0];   // residuals (B*S, N, D)
    const float* gamma  = (const float*)d_in[1];   // (S*D,)
    const float* salpha = (const float*)d_in[2];   // (S+T,) = 14
    const float* Wa     = (const float*)d_in[3];   // (S*D, 14)
    const float* pbs    = (const float*)d_in[4];   // (1,)
    const float* rs     = (const float*)d_in[5];   // (1,)
    const float* sbeta  = (const float*)d_in[6];   // (S,) = 8
    const float* Wb     = (const float*)d_in[7];   // (S*D, 8)
    const float* hps    = (const float*)d_in[8];   // scalar
    float* out = (float*)d_out;

    k_prepW<<<(KT_TOT * 12 * 32 + 255) / 256, 256>>>(gamma, Wa, Wb);
    k_reduce<<<dim3(MT, KC), 256>>>(resid);
    k_mix<<<BN / 256, 256>>>(salpha, pbs, rs, sbeta, hps);
    k_apply<<<dim3(BN, 2), 256>>>(resid, out);
}